// round 10
// baseline (speedup 1.0000x reference)
#include <cuda_runtime.h>
#include <math.h>

#define IMG_W 512
#define IMG_H 512
#define NPLANE 48
#define PLANE (IMG_W * IMG_H)
#define TOT (NPLANE * PLANE)

#define T_V 32
#define EPSF 1e-8f

// ---------------------------------------------------------------------------
// Scratch (__device__ globals). RULE learned R4-R9: these symbols must NEVER
// appear in a host-side launch argument list (host sees the shadow symbol,
// kernels then write through a host address via ATS -> +256MiB UVM backing ->
// harness guard). They are referenced from device code only.
// Footprint kept at R3-proven ~192 MiB: g_log is overwritten in-place with
// the reflectance by pass_hc.
// ---------------------------------------------------------------------------
__device__ float g_log[TOT];           // log(rgb+eps); becomes refl after pass_hc
__device__ float g_v0[TOT];            // vertical blur sigma=2 of g_log
__device__ float g_v1[TOT];            // sigma=4
__device__ float g_v2[TOT];            // sigma=8
__device__ float2 g_part[NPLANE * IMG_H];
__device__ float2 g_stats[NPLANE];

// ---------------------------------------------------------------------------
// Compile-time Gaussian coefficients
// ---------------------------------------------------------------------------
__host__ __device__ constexpr double cexp(double x) {
    double t = 1.0, s = 1.0;
    for (int k = 1; k < 60; k++) { t *= x / (double)k; s += t; }
    return s;
}

template <int R>
struct Gauss {
    float c[2 * R + 1];
    __host__ __device__ constexpr Gauss(double sigma, double wmul) : c{} {
        double S = 0.0;
        for (int i = -R; i <= R; i++)
            S += cexp(-(double)(i * i) / (2.0 * sigma * sigma));
        for (int i = -R; i <= R; i++)
            c[i + R] = (float)(wmul * cexp(-(double)(i * i) / (2.0 * sigma * sigma)) / S);
    }
};

// ---------------------------------------------------------------------------
// Pass L: elementwise log(rgb + eps) -> g_log
// ---------------------------------------------------------------------------
__global__ __launch_bounds__(256) void pass_l(const float* __restrict__ rgb) {
    const unsigned i = (blockIdx.x * 256u + threadIdx.x) * 4u;
    float4 v = *reinterpret_cast<const float4*>(rgb + i);
    float4 o;
    o.x = logf(v.x + EPSF);
    o.y = logf(v.y + EPSF);
    o.z = logf(v.z + EPSF);
    o.w = logf(v.w + EPSF);
    *reinterpret_cast<float4*>(&g_log[i]) = o;
}

// ---------------------------------------------------------------------------
// Vertical blur worker. Thread = one column, T_V rows, register window.
// dst is bound to a __device__ global INSIDE the calling kernel (device code).
// ---------------------------------------------------------------------------
template <int R>
__device__ __forceinline__ void vrun(float* __restrict__ dst, const Gauss<R>& C) {
    const int x = blockIdx.x * 256 + threadIdx.x;
    const int y0 = blockIdx.y * T_V;
    const int plane = blockIdx.z;
    const float* src = g_log + (size_t)plane * PLANE;
    float* out = dst + (size_t)plane * PLANE;

    float w[2 * R + 1];
#pragma unroll
    for (int j = 0; j < 2 * R; j++) {
        int y = y0 - R + j;
        w[j] = (y >= 0 && y < IMG_H) ? src[y * IMG_W + x] : 0.0f;
    }
#pragma unroll
    for (int t = 0; t < T_V; t++) {
        int y = y0 + t + R;
        w[2 * R] = (y < IMG_H) ? src[y * IMG_W + x] : 0.0f;
        float s = 0.0f;
#pragma unroll
        for (int j = 0; j < 2 * R + 1; j++) s = fmaf(w[j], C.c[j], s);
        out[(y0 + t) * IMG_W + x] = s;
#pragma unroll
        for (int j = 0; j < 2 * R; j++) w[j] = w[j + 1];
    }
}

__global__ __launch_bounds__(256) void pass_v2() {
    constexpr Gauss<6> C(2.0, 1.0);
    vrun<6>(g_v0, C);
}
__global__ __launch_bounds__(256) void pass_v4() {
    constexpr Gauss<12> C(4.0, 1.0);
    vrun<12>(g_v1, C);
}
__global__ __launch_bounds__(256) void pass_v8() {
    constexpr Gauss<24> C(8.0, 1.0);
    vrun<24>(g_v2, C);
}

// ---------------------------------------------------------------------------
// Pass HC: horizontal blurs of the three v-fields (weights folded in),
// phased through ONE shared buffer with __syncthreads() between sigmas.
// refl overwrites g_log in place (each block reads g_log only at its own row
// before the overwrite). One block per (plane, row); 128 threads x 4 px.
// ---------------------------------------------------------------------------
__global__ __launch_bounds__(128) void pass_hc() {
    constexpr Gauss<6>  C0(2.0, 1.0 / 2.25);
    constexpr Gauss<12> C1(4.0, 0.75 / 2.25);
    constexpr Gauss<24> C2(8.0, 0.5 / 2.25);

    __shared__ __align__(16) float s[560];
    __shared__ float ssum[4], ssq[4];

    const int plane = blockIdx.y;
    const int y = blockIdx.x;
    const int tid = threadIdx.x;
    const size_t ro = (size_t)plane * PLANE + (size_t)y * IMG_W;
    const int x0 = tid * 4;

    float il[4] = {0.0f, 0.0f, 0.0f, 0.0f};

    // ---- phase sigma=8 ----
    for (int i = tid; i < 560; i += 128) {
        int x = i - 24;
        s[i] = (x >= 0 && x < IMG_W) ? g_v2[ro + x] : 0.0f;
    }
    __syncthreads();
    {
        float w[52];
        const float4* p4 = reinterpret_cast<const float4*>(s + x0);
#pragma unroll
        for (int j = 0; j < 13; j++) {
            float4 v = p4[j];
            w[4 * j] = v.x; w[4 * j + 1] = v.y; w[4 * j + 2] = v.z; w[4 * j + 3] = v.w;
        }
#pragma unroll
        for (int p = 0; p < 4; p++) {
            float a = 0.0f;
#pragma unroll
            for (int j = 0; j < 49; j++) a = fmaf(w[p + j], C2.c[j], a);
            il[p] += a;
        }
    }
    __syncthreads();

    // ---- phase sigma=4 ----
    for (int i = tid; i < 560; i += 128) {
        int x = i - 24;
        s[i] = (x >= 0 && x < IMG_W) ? g_v1[ro + x] : 0.0f;
    }
    __syncthreads();
    {
        float w[28];
        const float4* p4 = reinterpret_cast<const float4*>(s + x0 + 12);
#pragma unroll
        for (int j = 0; j < 7; j++) {
            float4 v = p4[j];
            w[4 * j] = v.x; w[4 * j + 1] = v.y; w[4 * j + 2] = v.z; w[4 * j + 3] = v.w;
        }
#pragma unroll
        for (int p = 0; p < 4; p++) {
            float a = 0.0f;
#pragma unroll
            for (int j = 0; j < 25; j++) a = fmaf(w[p + j], C1.c[j], a);
            il[p] += a;
        }
    }
    __syncthreads();

    // ---- phase sigma=2 ----
    for (int i = tid; i < 560; i += 128) {
        int x = i - 24;
        s[i] = (x >= 0 && x < IMG_W) ? g_v0[ro + x] : 0.0f;
    }
    __syncthreads();
    {
        float w[20];
        const float4* p4 = reinterpret_cast<const float4*>(s + x0 + 16);
#pragma unroll
        for (int j = 0; j < 5; j++) {
            float4 v = p4[j];
            w[4 * j] = v.x; w[4 * j + 1] = v.y; w[4 * j + 2] = v.z; w[4 * j + 3] = v.w;
        }
#pragma unroll
        for (int p = 0; p < 4; p++) {
            float a = 0.0f;
#pragma unroll
            for (int j = 0; j < 13; j++) a = fmaf(w[p + 2 + j], C0.c[j], a);
            il[p] += a;
        }
    }

    // ---- reflectance (in place over g_log) + per-row stats partial ----
    const float4 lg4 = *reinterpret_cast<const float4*>(g_log + ro + x0);
    float r[4];
    r[0] = lg4.x - il[0];
    r[1] = lg4.y - il[1];
    r[2] = lg4.z - il[2];
    r[3] = lg4.w - il[3];

    *reinterpret_cast<float4*>(&g_log[ro + x0]) = make_float4(r[0], r[1], r[2], r[3]);

    float psum = 0.0f, psq = 0.0f;
#pragma unroll
    for (int p = 0; p < 4; p++) { psum += r[p]; psq = fmaf(r[p], r[p], psq); }

#pragma unroll
    for (int off = 16; off; off >>= 1) {
        psum += __shfl_down_sync(0xffffffffu, psum, off);
        psq  += __shfl_down_sync(0xffffffffu, psq, off);
    }
    const int lane = tid & 31, wid = tid >> 5;
    if (lane == 0) { ssum[wid] = psum; ssq[wid] = psq; }
    __syncthreads();
    if (tid == 0) {
        float a = 0.0f, b = 0.0f;
#pragma unroll
        for (int i = 0; i < 4; i++) { a += ssum[i]; b += ssq[i]; }
        g_part[plane * IMG_H + y] = make_float2(a, b);
    }
}

// ---------------------------------------------------------------------------
// Stats: fold 512 row-partials per plane -> mean, 1/(std+eps).  ddof = 1.
// ---------------------------------------------------------------------------
__global__ __launch_bounds__(256) void reduce_stats() {
    const int plane = blockIdx.x;
    const int tid = threadIdx.x;
    float2 a = g_part[plane * IMG_H + tid];
    float2 b = g_part[plane * IMG_H + tid + 256];
    float s = a.x + b.x, q = a.y + b.y;
#pragma unroll
    for (int off = 16; off; off >>= 1) {
        s += __shfl_down_sync(0xffffffffu, s, off);
        q += __shfl_down_sync(0xffffffffu, q, off);
    }
    __shared__ float ssum[8], ssq[8];
    const int lane = tid & 31, wid = tid >> 5;
    if (lane == 0) { ssum[wid] = s; ssq[wid] = q; }
    __syncthreads();
    if (tid == 0) {
        float S = 0.0f, Q = 0.0f;
#pragma unroll
        for (int i = 0; i < 8; i++) { S += ssum[i]; Q += ssq[i]; }
        const float N = (float)PLANE;
        float mean = S / N;
        float var = (Q - S * S / N) / (N - 1.0f);
        float stdv = sqrtf(var);
        g_stats[plane] = make_float2(mean, 1.0f / (stdv + EPSF));
    }
}

// ---------------------------------------------------------------------------
// Pass F: normalize, exp, clip to [0,1].  (g_log now holds refl.)
// ---------------------------------------------------------------------------
__global__ __launch_bounds__(256) void pass_f(float* __restrict__ out) {
    const unsigned i = (blockIdx.x * 256u + threadIdx.x) * 4u;
    const unsigned plane = i >> 18;
    const float2 st = g_stats[plane];
    const float mean = st.x, inv = st.y;

    float4 r = *reinterpret_cast<const float4*>(&g_log[i]);
    float4 o;
    o.x = fminf(expf((r.x - mean) * inv), 1.0f);
    o.y = fminf(expf((r.y - mean) * inv), 1.0f);
    o.z = fminf(expf((r.z - mean) * inv), 1.0f);
    o.w = fminf(expf((r.w - mean) * inv), 1.0f);
    *reinterpret_cast<float4*>(&out[i]) = o;
}

// ---------------------------------------------------------------------------
// Launch — note: NO __device__ symbol ever appears in an argument list here.
// ---------------------------------------------------------------------------
extern "C" void kernel_launch(void* const* d_in, const int* in_sizes, int n_in,
                              void* d_out, int out_size) {
    const float* rgb = (const float*)d_in[0];
    float* out = (float*)d_out;

    pass_l<<<TOT / 1024, 256>>>(rgb);

    dim3 gv(2, IMG_H / T_V, NPLANE);
    pass_v2<<<gv, 256>>>();
    pass_v4<<<gv, 256>>>();
    pass_v8<<<gv, 256>>>();

    pass_hc<<<dim3(IMG_H, NPLANE), 128>>>();

    reduce_stats<<<NPLANE, 256>>>();

    pass_f<<<TOT / 1024, 256>>>(out);
}

// round 11
// speedup vs baseline: 1.3774x; 1.3774x over previous
#include <cuda_runtime.h>
#include <math.h>

#define IMG_W 512
#define IMG_H 512
#define NPLANE 48
#define PLANE (IMG_W * IMG_H)
#define TOT (NPLANE * PLANE)

#define T_V 32
#define EPSF 1e-8f

// ---------------------------------------------------------------------------
// Scratch (__device__ globals). RULE (R4-R9): these symbols must NEVER appear
// in a host-side launch argument list (host shadow symbol -> ATS writes ->
// +256MiB UVM backing -> harness guard). Device-code references only.
// g_log is overwritten in-place with reflectance by pass_hc.
// ---------------------------------------------------------------------------
__device__ float g_log[TOT];           // log(rgb+eps); becomes refl after pass_hc
__device__ float g_v0[TOT];            // vertical blur sigma=2
__device__ float g_v1[TOT];            // sigma=4
__device__ float g_v2[TOT];            // sigma=8
__device__ float2 g_part[NPLANE * IMG_H];
__device__ float2 g_stats[NPLANE];

// ---------------------------------------------------------------------------
// Compile-time Gaussian coefficients (constructed only with literal args in
// non-template kernels).
// ---------------------------------------------------------------------------
__host__ __device__ constexpr double cexp(double x) {
    double t = 1.0, s = 1.0;
    for (int k = 1; k < 60; k++) { t *= x / (double)k; s += t; }
    return s;
}

template <int R>
struct Gauss {
    float c[2 * R + 1];
    __host__ __device__ constexpr Gauss(double sigma, double wmul) : c{} {
        double S = 0.0;
        for (int i = -R; i <= R; i++)
            S += cexp(-(double)(i * i) / (2.0 * sigma * sigma));
        for (int i = -R; i <= R; i++)
            c[i + R] = (float)(wmul * cexp(-(double)(i * i) / (2.0 * sigma * sigma)) / S);
    }
};

// ---------------------------------------------------------------------------
// Pass L: elementwise log(rgb + eps) -> g_log
// ---------------------------------------------------------------------------
__global__ __launch_bounds__(256) void pass_l(const float* __restrict__ rgb) {
    const unsigned i = (blockIdx.x * 256u + threadIdx.x) * 4u;
    float4 v = *reinterpret_cast<const float4*>(rgb + i);
    float4 o;
    o.x = logf(v.x + EPSF);
    o.y = logf(v.y + EPSF);
    o.z = logf(v.z + EPSF);
    o.w = logf(v.w + EPSF);
    *reinterpret_cast<float4*>(&g_log[i]) = o;
}

// ---------------------------------------------------------------------------
// Pass VF: FUSED vertical blurs (all three sigmas share one 49-float window).
// Thread = one column, T_V output rows. One load stream instead of three.
// sigma=2 taps = w[18..30], sigma=4 = w[12..36], sigma=8 = w[0..48].
// ---------------------------------------------------------------------------
__global__ __launch_bounds__(256) void pass_vf() {
    constexpr Gauss<6>  C0(2.0, 1.0);
    constexpr Gauss<12> C1(4.0, 1.0);
    constexpr Gauss<24> C2(8.0, 1.0);

    const int x = blockIdx.x * 256 + threadIdx.x;
    const int y0 = blockIdx.y * T_V;
    const int plane = blockIdx.z;
    const size_t po = (size_t)plane * PLANE;
    const float* src = g_log + po;

    float w[49];
#pragma unroll
    for (int j = 0; j < 48; j++) {
        int y = y0 - 24 + j;
        w[j] = (y >= 0 && y < IMG_H) ? src[y * IMG_W + x] : 0.0f;
    }
#pragma unroll
    for (int t = 0; t < T_V; t++) {
        int y = y0 + t + 24;
        w[48] = (y < IMG_H) ? src[y * IMG_W + x] : 0.0f;

        float s2 = 0.0f, s1 = 0.0f, s0 = 0.0f;
#pragma unroll
        for (int j = 0; j < 49; j++) s2 = fmaf(w[j], C2.c[j], s2);
#pragma unroll
        for (int j = 0; j < 25; j++) s1 = fmaf(w[12 + j], C1.c[j], s1);
#pragma unroll
        for (int j = 0; j < 13; j++) s0 = fmaf(w[18 + j], C0.c[j], s0);

        const size_t o = po + (size_t)(y0 + t) * IMG_W + x;
        g_v2[o] = s2;
        g_v1[o] = s1;
        g_v0[o] = s0;
#pragma unroll
        for (int j = 0; j < 48; j++) w[j] = w[j + 1];
    }
}

// ---------------------------------------------------------------------------
// Pass HC: horizontal blurs of the three v-fields (weights folded in),
// all three rows loaded into smem in ONE phase with ONE barrier; sigma
// windows consumed in scoped live ranges. refl overwrites g_log in place.
// One block per (plane, row); 128 threads x 4 px.
// ---------------------------------------------------------------------------
__global__ __launch_bounds__(128) void pass_hc() {
    constexpr Gauss<6>  C0(2.0, 1.0 / 2.25);
    constexpr Gauss<12> C1(4.0, 0.75 / 2.25);
    constexpr Gauss<24> C2(8.0, 0.5 / 2.25);

    __shared__ __align__(16) float s0[560], s1[560], s2[560];
    __shared__ float ssum[4], ssq[4];

    const int plane = blockIdx.y;
    const int y = blockIdx.x;
    const int tid = threadIdx.x;
    const size_t ro = (size_t)plane * PLANE + (size_t)y * IMG_W;
    const int x0 = tid * 4;

    for (int i = tid; i < 560; i += 128) {
        int x = i - 24;
        bool in = (x >= 0 && x < IMG_W);
        s0[i] = in ? g_v0[ro + x] : 0.0f;
        s1[i] = in ? g_v1[ro + x] : 0.0f;
        s2[i] = in ? g_v2[ro + x] : 0.0f;
    }
    __syncthreads();

    float il[4] = {0.0f, 0.0f, 0.0f, 0.0f};

    {   // sigma=8: window s2[x0 .. x0+51]
        float w[52];
        const float4* p4 = reinterpret_cast<const float4*>(s2 + x0);
#pragma unroll
        for (int j = 0; j < 13; j++) {
            float4 v = p4[j];
            w[4 * j] = v.x; w[4 * j + 1] = v.y; w[4 * j + 2] = v.z; w[4 * j + 3] = v.w;
        }
#pragma unroll
        for (int p = 0; p < 4; p++) {
            float a = 0.0f;
#pragma unroll
            for (int j = 0; j < 49; j++) a = fmaf(w[p + j], C2.c[j], a);
            il[p] += a;
        }
    }
    {   // sigma=4: window s1[x0+12 .. x0+39]
        float w[28];
        const float4* p4 = reinterpret_cast<const float4*>(s1 + x0 + 12);
#pragma unroll
        for (int j = 0; j < 7; j++) {
            float4 v = p4[j];
            w[4 * j] = v.x; w[4 * j + 1] = v.y; w[4 * j + 2] = v.z; w[4 * j + 3] = v.w;
        }
#pragma unroll
        for (int p = 0; p < 4; p++) {
            float a = 0.0f;
#pragma unroll
            for (int j = 0; j < 25; j++) a = fmaf(w[p + j], C1.c[j], a);
            il[p] += a;
        }
    }
    {   // sigma=2: window s0[x0+16 .. x0+35], taps at [2..17]
        float w[20];
        const float4* p4 = reinterpret_cast<const float4*>(s0 + x0 + 16);
#pragma unroll
        for (int j = 0; j < 5; j++) {
            float4 v = p4[j];
            w[4 * j] = v.x; w[4 * j + 1] = v.y; w[4 * j + 2] = v.z; w[4 * j + 3] = v.w;
        }
#pragma unroll
        for (int p = 0; p < 4; p++) {
            float a = 0.0f;
#pragma unroll
            for (int j = 0; j < 13; j++) a = fmaf(w[p + 2 + j], C0.c[j], a);
            il[p] += a;
        }
    }

    // refl (in place over g_log) + per-row stats partial
    const float4 lg4 = *reinterpret_cast<const float4*>(g_log + ro + x0);
    float r[4];
    r[0] = lg4.x - il[0];
    r[1] = lg4.y - il[1];
    r[2] = lg4.z - il[2];
    r[3] = lg4.w - il[3];

    *reinterpret_cast<float4*>(&g_log[ro + x0]) = make_float4(r[0], r[1], r[2], r[3]);

    float psum = 0.0f, psq = 0.0f;
#pragma unroll
    for (int p = 0; p < 4; p++) { psum += r[p]; psq = fmaf(r[p], r[p], psq); }

#pragma unroll
    for (int off = 16; off; off >>= 1) {
        psum += __shfl_down_sync(0xffffffffu, psum, off);
        psq  += __shfl_down_sync(0xffffffffu, psq, off);
    }
    const int lane = tid & 31, wid = tid >> 5;
    if (lane == 0) { ssum[wid] = psum; ssq[wid] = psq; }
    __syncthreads();
    if (tid == 0) {
        float a = 0.0f, b = 0.0f;
#pragma unroll
        for (int i = 0; i < 4; i++) { a += ssum[i]; b += ssq[i]; }
        g_part[plane * IMG_H + y] = make_float2(a, b);
    }
}

// ---------------------------------------------------------------------------
// Stats: fold 512 row-partials per plane -> mean, 1/(std+eps).  ddof = 1.
// ---------------------------------------------------------------------------
__global__ __launch_bounds__(256) void reduce_stats() {
    const int plane = blockIdx.x;
    const int tid = threadIdx.x;
    float2 a = g_part[plane * IMG_H + tid];
    float2 b = g_part[plane * IMG_H + tid + 256];
    float s = a.x + b.x, q = a.y + b.y;
#pragma unroll
    for (int off = 16; off; off >>= 1) {
        s += __shfl_down_sync(0xffffffffu, s, off);
        q += __shfl_down_sync(0xffffffffu, q, off);
    }
    __shared__ float ssum[8], ssq[8];
    const int lane = tid & 31, wid = tid >> 5;
    if (lane == 0) { ssum[wid] = s; ssq[wid] = q; }
    __syncthreads();
    if (tid == 0) {
        float S = 0.0f, Q = 0.0f;
#pragma unroll
        for (int i = 0; i < 8; i++) { S += ssum[i]; Q += ssq[i]; }
        const float N = (float)PLANE;
        float mean = S / N;
        float var = (Q - S * S / N) / (N - 1.0f);
        float stdv = sqrtf(var);
        g_stats[plane] = make_float2(mean, 1.0f / (stdv + EPSF));
    }
}

// ---------------------------------------------------------------------------
// Pass F: normalize, exp, clip to [0,1].  (g_log now holds refl.)
// ---------------------------------------------------------------------------
__global__ __launch_bounds__(256) void pass_f(float* __restrict__ out) {
    const unsigned i = (blockIdx.x * 256u + threadIdx.x) * 4u;
    const unsigned plane = i >> 18;
    const float2 st = g_stats[plane];
    const float mean = st.x, inv = st.y;

    float4 r = *reinterpret_cast<const float4*>(&g_log[i]);
    float4 o;
    o.x = fminf(expf((r.x - mean) * inv), 1.0f);
    o.y = fminf(expf((r.y - mean) * inv), 1.0f);
    o.z = fminf(expf((r.z - mean) * inv), 1.0f);
    o.w = fminf(expf((r.w - mean) * inv), 1.0f);
    *reinterpret_cast<float4*>(&out[i]) = o;
}

// ---------------------------------------------------------------------------
// Launch — NO __device__ symbol ever appears in an argument list.
// ---------------------------------------------------------------------------
extern "C" void kernel_launch(void* const* d_in, const int* in_sizes, int n_in,
                              void* d_out, int out_size) {
    const float* rgb = (const float*)d_in[0];
    float* out = (float*)d_out;

    pass_l<<<TOT / 1024, 256>>>(rgb);

    pass_vf<<<dim3(2, IMG_H / T_V, NPLANE), 256>>>();

    pass_hc<<<dim3(IMG_H, NPLANE), 128>>>();

    reduce_stats<<<NPLANE, 256>>>();

    pass_f<<<TOT / 1024, 256>>>(out);
}